// round 6
// baseline (speedup 1.0000x reference)
#include <cuda_runtime.h>
#include <cstdint>

#define N_NODES 8192
#define F_IN    1024
#define F_OUT   512

// ---------------- device scratch ----------------
__device__ float    g_S [N_NODES * F_OUT];   // seq_fts fp32 (16 MB) for k2
__device__ unsigned g_Bt[F_OUT * N_NODES];   // seq_fts tf32, n-major + k4 fragment layout
__device__ float    g_f1[N_NODES];
__device__ float    g_f2[N_NODES];

// ---------------- helpers ----------------
__device__ __forceinline__ float fast_exp(float x) {
    float t = x * 1.4426950408889634f;
    t = fminf(fmaxf(t, -126.0f), 126.0f);
    float fi = rintf(t);
    float f  = t - fi;
    float p  =          1.5403530393381609e-4f;
    p = fmaf(p, f, 1.3333558146428443e-3f);
    p = fmaf(p, f, 9.6181291076284772e-3f);
    p = fmaf(p, f, 5.5504108664821580e-2f);
    p = fmaf(p, f, 2.4022650695910071e-1f);
    p = fmaf(p, f, 6.9314718055994531e-1f);
    p = fmaf(p, f, 1.0f);
    int e = (int)fi;
    return p * __int_as_float((e + 127) << 23);
}

__device__ __forceinline__ unsigned tf32_of(float x) {
    unsigned r;
    asm("cvt.rna.tf32.f32 %0, %1;" : "=r"(r) : "f"(x));
    return r;
}

__device__ __forceinline__ void mma_tf32(float* d, const unsigned* a, const unsigned* b) {
    asm volatile(
        "mma.sync.aligned.m16n8k8.row.col.f32.tf32.tf32.f32 "
        "{%0,%1,%2,%3}, {%4,%5,%6,%7}, {%8,%9}, {%0,%1,%2,%3};"
        : "+f"(d[0]), "+f"(d[1]), "+f"(d[2]), "+f"(d[3])
        : "r"(a[0]), "r"(a[1]), "r"(a[2]), "r"(a[3]), "r"(b[0]), "r"(b[1]));
}

__device__ __forceinline__ void cp16(void* smem_ptr, const void* gptr) {
    unsigned sa = (unsigned)__cvta_generic_to_shared(smem_ptr);
    asm volatile("cp.async.cg.shared.global [%0], [%1], 16;" :: "r"(sa), "l"(gptr));
}
__device__ __forceinline__ void cp_commit() { asm volatile("cp.async.commit_group;"); }
__device__ __forceinline__ void cp_wait1()  { asm volatile("cp.async.wait_group 1;"); }

// ---------------- K1: seq_fts = x @ seq_W.T (single tf32) ------------------
// Epilogue also writes g_Bt: n-major tf32 with k4's fragment interleave:
// g_Bt[f*8192 + (j&~31) + (((j>>4)&1)^(f&1))*16 + (j&3)*4 + ((j>>2)&3)]
__global__ __launch_bounds__(256) void k1_seqfts(const float* __restrict__ X,
                                                 const float* __restrict__ W) {
    __shared__ float As[128][36];
    __shared__ float Bs[64][36];
    const int tid = threadIdx.x;
    const int m0 = blockIdx.y * 128;
    const int n0 = blockIdx.x * 64;
    const int warp = tid >> 5, lane = tid & 31;
    const int grp = lane >> 2, tig = lane & 3;
    const int wm = warp & 3, wn = warp >> 2;
    const int lr = tid >> 3;
    const int lc = (tid & 7) << 2;

    float d[2][4][4];
#pragma unroll
    for (int i = 0; i < 2; i++)
#pragma unroll
        for (int j = 0; j < 4; j++)
#pragma unroll
            for (int q = 0; q < 4; q++) d[i][j][q] = 0.0f;

    for (int k0 = 0; k0 < F_IN; k0 += 32) {
#pragma unroll
        for (int p = 0; p < 4; p++) {
            float4 v = *(const float4*)&X[(size_t)(m0 + lr + p * 32) * F_IN + k0 + lc];
            *(float4*)&As[lr + p * 32][lc] = v;
        }
#pragma unroll
        for (int p = 0; p < 2; p++) {
            float4 v = *(const float4*)&W[(size_t)(n0 + lr + p * 32) * F_IN + k0 + lc];
            *(float4*)&Bs[lr + p * 32][lc] = v;
        }
        __syncthreads();
#pragma unroll
        for (int kk = 0; kk < 32; kk += 8) {
            unsigned ah[2][4];
#pragma unroll
            for (int mt = 0; mt < 2; mt++) {
                int rb = wm * 32 + mt * 16;
                ah[mt][0] = tf32_of(As[rb + grp][kk + tig]);
                ah[mt][1] = tf32_of(As[rb + grp + 8][kk + tig]);
                ah[mt][2] = tf32_of(As[rb + grp][kk + tig + 4]);
                ah[mt][3] = tf32_of(As[rb + grp + 8][kk + tig + 4]);
            }
            unsigned bh[4][2];
#pragma unroll
            for (int nt = 0; nt < 4; nt++) {
                int cb = wn * 32 + nt * 8;
                bh[nt][0] = tf32_of(Bs[cb + grp][kk + tig]);
                bh[nt][1] = tf32_of(Bs[cb + grp][kk + tig + 4]);
            }
#pragma unroll
            for (int mt = 0; mt < 2; mt++)
#pragma unroll
                for (int nt = 0; nt < 4; nt++)
                    mma_tf32(d[mt][nt], ah[mt], bh[nt]);
        }
        __syncthreads();
    }
    const int ilo = (grp & 3) * 4 + (grp >> 2);
#pragma unroll
    for (int mt = 0; mt < 2; mt++)
#pragma unroll
        for (int nt = 0; nt < 4; nt++) {
            int r = m0 + wm * 32 + mt * 16 + grp;
            int c = n0 + wn * 32 + nt * 8 + tig * 2;
            size_t i00 = (size_t)r * F_OUT + c;
            size_t i10 = (size_t)(r + 8) * F_OUT + c;
            g_S[i00]     = d[mt][nt][0];
            g_S[i00 + 1] = d[mt][nt][1];
            g_S[i10]     = d[mt][nt][2];
            g_S[i10 + 1] = d[mt][nt][3];
            // g_Bt fragment layout (c even; c+1 flips the parity block)
            size_t jb = (size_t)(m0 + wm * 32);
            size_t b0 = (size_t)c * 8192 + jb + (mt << 4) + ilo;
            size_t b1 = (size_t)(c + 1) * 8192 + jb + ((mt ^ 1) << 4) + ilo;
            g_Bt[b0]     = tf32_of(d[mt][nt][0]);
            g_Bt[b0 + 2] = tf32_of(d[mt][nt][2]);   // row r+8 -> il +2
            g_Bt[b1]     = tf32_of(d[mt][nt][1]);
            g_Bt[b1 + 2] = tf32_of(d[mt][nt][3]);
        }
}

// ---------------- K2: f1/f2 projections -------------------------------------
__global__ __launch_bounds__(256) void k2_fvec(const float* __restrict__ f1w,
                                               const float* __restrict__ f1b,
                                               const float* __restrict__ f2w,
                                               const float* __restrict__ f2b) {
    int row = blockIdx.x * 8 + (threadIdx.x >> 5);
    int lane = threadIdx.x & 31;
    const float* Sr = g_S + (size_t)row * F_OUT;
    float s1 = 0.f, s2 = 0.f;
    for (int c = lane; c < F_OUT; c += 32) {
        float v = Sr[c];
        s1 = fmaf(v, f1w[c], s1);
        s2 = fmaf(v, f2w[c], s2);
    }
#pragma unroll
    for (int o = 16; o > 0; o >>= 1) {
        s1 += __shfl_xor_sync(0xffffffff, s1, o);
        s2 += __shfl_xor_sync(0xffffffff, s2, o);
    }
    if (lane == 0) {
        g_f1[row] = s1 + f1b[0];
        g_f2[row] = s2 + f2b[0];
    }
}

// ---------------- K3: RWR ----------------------------------------------------
__global__ __launch_bounds__(256) void k3_rwr(const int* __restrict__ adj_ad,
                                              float* __restrict__ out_ri,
                                              int write_ri) {
    const int i = blockIdx.x;
    const int tid = threadIdx.x;
    const int4* crow = (const int4*)(adj_ad + (size_t)i * N_NODES);
    int cnt = 0;
    for (int j4 = tid; j4 < N_NODES / 4; j4 += 256) {
        int4 c = crow[j4];
        cnt += (c.x == 2 || c.x == 3);
        cnt += (c.y == 2 || c.y == 3);
        cnt += (c.z == 2 || c.z == 3);
        cnt += (c.w == 2 || c.w == 3);
    }
    __shared__ int sc[256];
    sc[tid] = cnt;
    __syncthreads();
    for (int s = 128; s > 0; s >>= 1) {
        if (tid < s) sc[tid] += sc[tid + s];
        __syncthreads();
    }
    if (tid == 0 && write_ri) {
        float k = (float)sc[0];
        float den = 1.0f - 0.25f * k;
        float r0, rn;
        if (den == 0.0f) { r0 = 1.0f; rn = 0.5f; }
        else             { r0 = fabsf(1.0f / den); rn = fabsf(0.5f / den); }
        out_ri[2 * i]     = r0;
        out_ri[2 * i + 1] = rn;
    }
}

// ---------------- K4: fused attention GEMM  h = elu(P@S / Z + bias) --------
// 512 thr / 16 warps (2M x 8N, warp tile 64x32). Fragment-major P/B smem:
// rows padded to 36 words; within each 16-col block, il(o)=(o&3)*4+(o>>2),
// with per-row-parity block swap. A-frags: LDS.128; B-frags: LDS.128.
// adj + f2 prefetched in registers one slab ahead. B 4-deep cp.async.
#define BROW 36
#define BST  (256 * BROW)
#define PST  (128 * 36)
#define OFFB 0
#define OFFP (4 * BST)
#define OFFM (OFFP + 2 * PST)
#define K4_SMEM ((OFFM + 640) * 4)

__device__ __forceinline__ void k4_issueB(float* sm, int n0, int s, int tid) {
    float* Bb = sm + OFFB + (s & 3) * BST;
    const int j0 = s * 32;
#pragma unroll
    for (int k = 0; k < 4; k++) {                 // 256 rows x 32 words
        int idx = tid + k * 512;
        int r = idx >> 3, c = idx & 7;
        cp16(&Bb[r * BROW + c * 4], &g_Bt[(size_t)(n0 + r) * 8192 + j0 + c * 4]);
    }
}

__device__ __forceinline__ void pgen_store(const float4& a, unsigned* Pn, int cb,
                                           float f1v, const float4& f2v, float* z) {
    float l, e0, e1, e2, e3;
    l = f1v + f2v.x; l = l > 0.f ? l : 0.2f * l; e0 = fast_exp(l + a.x);
    l = f1v + f2v.y; l = l > 0.f ? l : 0.2f * l; e1 = fast_exp(l + a.y);
    l = f1v + f2v.z; l = l > 0.f ? l : 0.2f * l; e2 = fast_exp(l + a.z);
    l = f1v + f2v.w; l = l > 0.f ? l : 0.2f * l; e3 = fast_exp(l + a.w);
    *z += (e0 + e1) + (e2 + e3);
    Pn[cb]      = tf32_of(e0);
    Pn[cb + 4]  = tf32_of(e1);
    Pn[cb + 8]  = tf32_of(e2);
    Pn[cb + 12] = tf32_of(e3);
}

__global__ __launch_bounds__(512, 1) void k4_attn(const float* __restrict__ adj,
                                                  const float* __restrict__ bias,
                                                  float* __restrict__ out) {
    extern __shared__ float sm[];
    float* f1s   = sm + OFFM;          // 128
    float* zrow  = sm + OFFM + 128;    // 128
    float* rzs   = sm + OFFM + 256;    // 128
    float* sbias = sm + OFFM + 384;    // 256

    const int tid = threadIdx.x;
    const int m0 = blockIdx.y * 128;
    const int n0 = blockIdx.x * 256;
    const int warp = tid >> 5, lane = tid & 31;
    const int grp = lane >> 2, tig = lane & 3;
    const int wm = warp >> 3, wn = warp & 7;     // 2M x 8N, tiles 64x32
    const int gr = tid >> 3;                     // 0..63
    const int gc = (tid & 7) << 2;               // 0..28

    if (tid < 128) f1s[tid] = g_f1[m0 + tid];
    if (tid < 256) sbias[tid] = bias[n0 + tid];

    // pgen write offsets (row gr and gr+64, fixed per thread)
    const int cgrp = (gc >> 2) & 3;
    const int r0p = gr, r1p = gr + 64;
    const int cb0 = r0p * 36 + ((((gc >> 4) ^ (r0p & 1)) << 4)) + cgrp;
    const int cb1 = r1p * 36 + ((((gc >> 4) ^ (r1p & 1)) << 4)) + cgrp;

    float d[4][4][4];
#pragma unroll
    for (int mt = 0; mt < 4; mt++)
#pragma unroll
        for (int nt = 0; nt < 4; nt++)
#pragma unroll
            for (int q = 0; q < 4; q++) d[mt][nt][q] = 0.0f;
    float zacc[2] = {0.f, 0.f};

    // prologue: B stages 0,1; adj/f2 regs for slab 0
    k4_issueB(sm, n0, 0, tid); cp_commit();
    k4_issueB(sm, n0, 1, tid); cp_commit();
    const float* adjr0 = adj + (size_t)(m0 + r0p) * N_NODES + gc;
    const float* adjr1 = adj + (size_t)(m0 + r1p) * N_NODES + gc;
    float4 adjv0 = *(const float4*)adjr0;
    float4 adjv1 = *(const float4*)adjr1;
    float4 f2v   = *(const float4*)&g_f2[gc];
    cp_wait1();
    __syncthreads();
    const float f1v0 = f1s[r0p];
    const float f1v1 = f1s[r1p];

    // pgen slab 0 -> P buffer 0
    {
        unsigned* Pn = (unsigned*)(sm + OFFP);
        pgen_store(adjv0, Pn, cb0, f1v0, f2v, &zacc[0]);
        pgen_store(adjv1, Pn, cb1, f1v1, f2v, &zacc[1]);
    }
    // prefetch adj/f2 for slab 1
    adjv0 = *(const float4*)(adjr0 + 32);
    adjv1 = *(const float4*)(adjr1 + 32);
    f2v   = *(const float4*)&g_f2[32 + gc];

    const int blkbase = tig * 4;
    const int psw = (grp & 1);                   // row-parity for frag reads

    for (int s = 0; s < 256; s++) {
        if (s + 2 < 256) k4_issueB(sm, n0, s + 2, tid);
        cp_commit();
        cp_wait1();              // B(s+1) ready
        __syncthreads();         // publish B(s+1); P[(s+1)&1] free

        const unsigned* Pc = (const unsigned*)(sm + OFFP + (s & 1) * PST);
        const unsigned* Bc = (const unsigned*)(sm + OFFB + (s & 3) * BST);
        unsigned*       Pn = (unsigned*)(sm + OFFP + ((s + 1) & 1) * PST);
        const bool gen = (s + 1 < 256);
        const int jn = (s + 2) * 32;

#pragma unroll
        for (int kk16 = 0; kk16 < 2; kk16++) {
            if (gen) {
                if (kk16 == 0) {
                    pgen_store(adjv0, Pn, cb0, f1v0, f2v, &zacc[0]);
                    if (s + 2 < 256) adjv0 = *(const float4*)(adjr0 + jn);
                } else {
                    pgen_store(adjv1, Pn, cb1, f1v1, f2v, &zacc[1]);
                    if (s + 2 < 256) adjv1 = *(const float4*)(adjr1 + jn);
                }
            }
            const int blk = ((kk16 ^ psw) << 4) + blkbase;
            uint4 bb[4];
#pragma unroll
            for (int nt = 0; nt < 4; nt++)
                bb[nt] = *(const uint4*)&Bc[(wn * 32 + nt * 8 + grp) * BROW + blk];
#pragma unroll
            for (int mt = 0; mt < 4; mt++) {
                int ra = (wm * 64 + mt * 16 + grp) * 36 + blk;
                uint4 ae = *(const uint4*)&Pc[ra];
                uint4 ao = *(const uint4*)&Pc[ra + 8 * 36];
#pragma unroll
                for (int h = 0; h < 2; h++) {
                    unsigned av[4];
                    av[0] = h ? ae.z : ae.x;
                    av[1] = h ? ao.z : ao.x;
                    av[2] = h ? ae.w : ae.y;
                    av[3] = h ? ao.w : ao.y;
#pragma unroll
                    for (int nt = 0; nt < 4; nt++) {
                        unsigned bv[2];
                        bv[0] = h ? bb[nt].z : bb[nt].x;
                        bv[1] = h ? bb[nt].w : bb[nt].y;
                        mma_tf32(d[mt][nt], av, bv);
                    }
                }
            }
        }
        if (gen && (s + 2 < 256))
            f2v = *(const float4*)&g_f2[jn + gc];
    }

    // ---- Z reduction (8 threads per row) ----
#pragma unroll
    for (int m = 1; m < 8; m <<= 1)
#pragma unroll
        for (int p = 0; p < 2; p++)
            zacc[p] += __shfl_xor_sync(0xffffffff, zacc[p], m);
    if ((tid & 7) == 0) {
        zrow[r0p] = zacc[0];
        zrow[r1p] = zacc[1];
    }
    __syncthreads();
    if (tid < 128) rzs[tid] = 1.0f / zrow[tid];
    __syncthreads();

    // ---- epilogue: /Z, +bias, ELU ----
#pragma unroll
    for (int mt = 0; mt < 4; mt++) {
        int rl = wm * 64 + mt * 16 + grp;
        float rz0 = rzs[rl], rz1 = rzs[rl + 8];
        int gi = m0 + rl;
#pragma unroll
        for (int nt = 0; nt < 4; nt++) {
            int cl = wn * 32 + nt * 8 + tig * 2;
            int gf = n0 + cl;
            float b0 = sbias[cl], b1 = sbias[cl + 1];
            float v;
            v = fmaf(d[mt][nt][0], rz0, b0);
            out[(size_t)gi * F_OUT + gf]           = v > 0.f ? v : fast_exp(v) - 1.0f;
            v = fmaf(d[mt][nt][1], rz0, b1);
            out[(size_t)gi * F_OUT + gf + 1]       = v > 0.f ? v : fast_exp(v) - 1.0f;
            v = fmaf(d[mt][nt][2], rz1, b0);
            out[(size_t)(gi + 8) * F_OUT + gf]     = v > 0.f ? v : fast_exp(v) - 1.0f;
            v = fmaf(d[mt][nt][3], rz1, b1);
            out[(size_t)(gi + 8) * F_OUT + gf + 1] = v > 0.f ? v : fast_exp(v) - 1.0f;
        }
    }
}

// ---------------- launch ----------------
extern "C" void kernel_launch(void* const* d_in, const int* in_sizes, int n_in,
                              void* d_out, int out_size) {
    const float* x      = (const float*)d_in[0];
    const float* adj    = (const float*)d_in[1];
    const int*   adj_ad = (const int*)d_in[2];
    const float* seq_W  = (const float*)d_in[3];
    const float* f1w    = (const float*)d_in[4];
    const float* f1b    = (const float*)d_in[5];
    const float* f2w    = (const float*)d_in[6];
    const float* f2b    = (const float*)d_in[7];
    const float* bias   = (const float*)d_in[8];
    float* out = (float*)d_out;

    static int smem_set = 0;
    if (!smem_set) {
        cudaFuncSetAttribute(k4_attn, cudaFuncAttributeMaxDynamicSharedMemorySize, K4_SMEM);
        smem_set = 1;
    }

    k1_seqfts<<<dim3(8, 64), 256>>>(x, seq_W);
    k2_fvec<<<N_NODES / 8, 256>>>(f1w, f1b, f2w, f2b);
    int write_ri = (out_size >= N_NODES * F_OUT + 2 * N_NODES) ? 1 : 0;
    k3_rwr<<<N_NODES, 256>>>(adj_ad, out + (size_t)N_NODES * F_OUT, write_ri);
    k4_attn<<<dim3(2, 64), 512, K4_SMEM>>>(adj, bias, out);
}